// round 3
// baseline (speedup 1.0000x reference)
#include <cuda_runtime.h>
#include <math.h>

// Problem constants
#define B_SZ    2
#define S_LEN   2048
#define D_MODEL 1024
#define N_HEAD  16
#define D_HEAD  64
#define F_DIM   4096
#define M_ROWS  (B_SZ * S_LEN)   // 4096 token rows

// ---------------------------------------------------------------------------
// Scratch (device globals: allocation-free, graph-capture safe)
// ---------------------------------------------------------------------------
__device__ float g_q   [M_ROWS * D_MODEL];
__device__ float g_k   [M_ROWS * D_MODEL];
__device__ float g_v   [M_ROWS * D_MODEL];
__device__ float g_ctx [M_ROWS * D_MODEL];   // attn @ V
__device__ float g_tmp [M_ROWS * D_MODEL];   // Wo proj, then FFN2 output
__device__ float g_h1  [M_ROWS * D_MODEL];   // rmsnorm(x + attn_out)
__device__ float g_ffn1[M_ROWS * F_DIM];     // relu(h1 @ W1 + b1)

// ---------------------------------------------------------------------------
// Generic tiled SGEMM:  C = A(MxK) * op(B) + bias,  optional ReLU.
// TRANSB=false: B is (K x N) row-major.  TRANSB=true: B is (N x K) row-major
// (i.e. C = A * B^T).  Batched via blockIdx.z with (b, h) decomposed strides.
// All dims are multiples of the tile sizes for this problem -> no bounds checks.
// ---------------------------------------------------------------------------
template<int BM, int BN, int BK, int TM, int TN, bool TRANSB, bool RELU>
__global__ __launch_bounds__((BM / TM) * (BN / TN))
void gemm_kernel(const float* __restrict__ A, int lda,
                 const float* __restrict__ B, int ldb,
                 float*       __restrict__ C, int ldc,
                 int K, const float* __restrict__ bias,
                 int batchH,
                 long long sAb, long long sAh,
                 long long sBb, long long sBh,
                 long long sCb, long long sCh)
{
    constexpr int THREADS = (BM / TM) * (BN / TN);
    __shared__ float As[BK][BM];
    __shared__ float Bs[BK][BN];

    const int z  = blockIdx.z;
    const int zb = z / batchH;
    const int zh = z - zb * batchH;
    A += zb * sAb + zh * sAh;
    B += zb * sBb + zh * sBh;
    C += zb * sCb + zh * sCh;

    const int tid  = threadIdx.x;
    const int m0   = blockIdx.y * BM;
    const int n0   = blockIdx.x * BN;
    const int tcol = tid % (BN / TN);
    const int trow = tid / (BN / TN);

    float acc[TM][TN];
#pragma unroll
    for (int i = 0; i < TM; i++)
#pragma unroll
        for (int j = 0; j < TN; j++) acc[i][j] = 0.f;

    for (int k0 = 0; k0 < K; k0 += BK) {
        // --- stage A tile (BM x BK), transposed into As[k][m] ---
#pragma unroll
        for (int i = tid; i < BM * BK / 4; i += THREADS) {
            int r  = i / (BK / 4);
            int c4 = i % (BK / 4);
            float4 v4 = *reinterpret_cast<const float4*>(
                A + (long long)(m0 + r) * lda + k0 + c4 * 4);
            As[c4 * 4 + 0][r] = v4.x;
            As[c4 * 4 + 1][r] = v4.y;
            As[c4 * 4 + 2][r] = v4.z;
            As[c4 * 4 + 3][r] = v4.w;
        }
        // --- stage B tile into Bs[k][n] ---
        if (TRANSB) {
#pragma unroll
            for (int i = tid; i < BN * BK / 4; i += THREADS) {
                int r  = i / (BK / 4);     // n index
                int c4 = i % (BK / 4);
                float4 v4 = *reinterpret_cast<const float4*>(
                    B + (long long)(n0 + r) * ldb + k0 + c4 * 4);
                Bs[c4 * 4 + 0][r] = v4.x;
                Bs[c4 * 4 + 1][r] = v4.y;
                Bs[c4 * 4 + 2][r] = v4.z;
                Bs[c4 * 4 + 3][r] = v4.w;
            }
        } else {
#pragma unroll
            for (int i = tid; i < BK * BN / 4; i += THREADS) {
                int r  = i / (BN / 4);     // k index
                int c4 = i % (BN / 4);
                *reinterpret_cast<float4*>(&Bs[r][c4 * 4]) =
                    *reinterpret_cast<const float4*>(
                        B + (long long)(k0 + r) * ldb + n0 + c4 * 4);
            }
        }
        __syncthreads();

        // --- compute ---
#pragma unroll
        for (int kk = 0; kk < BK; kk++) {
            float a[TM], b[TN];
#pragma unroll
            for (int m = 0; m < TM; m += 4) {
                float4 t = *reinterpret_cast<const float4*>(&As[kk][trow * TM + m]);
                a[m] = t.x; a[m + 1] = t.y; a[m + 2] = t.z; a[m + 3] = t.w;
            }
#pragma unroll
            for (int n = 0; n < TN; n += 4) {
                float4 t = *reinterpret_cast<const float4*>(&Bs[kk][tcol * TN + n]);
                b[n] = t.x; b[n + 1] = t.y; b[n + 2] = t.z; b[n + 3] = t.w;
            }
#pragma unroll
            for (int m = 0; m < TM; m++)
#pragma unroll
                for (int n = 0; n < TN; n++)
                    acc[m][n] = fmaf(a[m], b[n], acc[m][n]);
        }
        __syncthreads();
    }

    // --- epilogue: bias + optional ReLU, float4 stores ---
#pragma unroll
    for (int m = 0; m < TM; m++) {
        long long crow = (long long)(m0 + trow * TM + m) * ldc + n0 + tcol * TN;
#pragma unroll
        for (int n = 0; n < TN; n += 4) {
            float4 v4;
            v4.x = acc[m][n];     v4.y = acc[m][n + 1];
            v4.z = acc[m][n + 2]; v4.w = acc[m][n + 3];
            if (bias) {
                int nb = n0 + tcol * TN + n;
                v4.x += bias[nb];     v4.y += bias[nb + 1];
                v4.z += bias[nb + 2]; v4.w += bias[nb + 3];
            }
            if (RELU) {
                v4.x = fmaxf(v4.x, 0.f); v4.y = fmaxf(v4.y, 0.f);
                v4.z = fmaxf(v4.z, 0.f); v4.w = fmaxf(v4.w, 0.f);
            }
            *reinterpret_cast<float4*>(C + crow + n) = v4;
        }
    }
}

// ---------------------------------------------------------------------------
// In-place masked softmax over the last dim (S_LEN) of attn[B,H,S,S].
// One block (256 threads) per row; scale applied before max/exp.
// ---------------------------------------------------------------------------
__global__ void softmax_kernel(float* __restrict__ attn,
                               const int* __restrict__ mask, float scale)
{
    const int r   = blockIdx.x;                 // 0 .. B*H*S-1
    const int b   = r / (N_HEAD * S_LEN);
    float*    row = attn + (long long)r * S_LEN;
    const int* mrow = mask + b * S_LEN;
    const int tid = threadIdx.x;
    constexpr int PER = S_LEN / 256;            // 8

    __shared__ float red[256];
    float vals[PER];
    float vmax = -INFINITY;
#pragma unroll
    for (int i = 0; i < PER; i++) {
        int j = i * 256 + tid;
        float v = row[j] * scale;
        if (mrow[j] == 0) v = -INFINITY;
        vals[i] = v;
        vmax = fmaxf(vmax, v);
    }
    red[tid] = vmax; __syncthreads();
    for (int s = 128; s > 0; s >>= 1) {
        if (tid < s) red[tid] = fmaxf(red[tid], red[tid + s]);
        __syncthreads();
    }
    vmax = red[0];
    __syncthreads();

    float sum = 0.f;
#pragma unroll
    for (int i = 0; i < PER; i++) {
        float e = expf(vals[i] - vmax);   // exp(-inf)=0 handles masked
        vals[i] = e;
        sum += e;
    }
    red[tid] = sum; __syncthreads();
    for (int s = 128; s > 0; s >>= 1) {
        if (tid < s) red[tid] += red[tid + s];
        __syncthreads();
    }
    float inv = 1.f / red[0];
#pragma unroll
    for (int i = 0; i < PER; i++)
        row[i * 256 + tid] = vals[i] * inv;
}

// ---------------------------------------------------------------------------
// out[r] = rmsnorm(xa[r] + xb[r], g) for rows of length D_MODEL.
// One block (256 threads, float4 per thread) per row.
// ---------------------------------------------------------------------------
__global__ void add_rmsnorm_kernel(const float* __restrict__ xa,
                                   const float* __restrict__ xb,
                                   const float* __restrict__ g,
                                   float*       __restrict__ out)
{
    const int r   = blockIdx.x;
    const int tid = threadIdx.x;            // 256 threads == D_MODEL/4
    const float4* a4 = reinterpret_cast<const float4*>(xa + (long long)r * D_MODEL);
    const float4* b4 = reinterpret_cast<const float4*>(xb + (long long)r * D_MODEL);
    const float4* g4 = reinterpret_cast<const float4*>(g);
    float4*       o4 = reinterpret_cast<float4*>(out + (long long)r * D_MODEL);

    float4 a = a4[tid], b = b4[tid];
    float4 s;
    s.x = a.x + b.x; s.y = a.y + b.y; s.z = a.z + b.z; s.w = a.w + b.w;
    float ss = s.x * s.x + s.y * s.y + s.z * s.z + s.w * s.w;

    __shared__ float red[256];
    red[tid] = ss; __syncthreads();
    for (int t = 128; t > 0; t >>= 1) {
        if (tid < t) red[tid] += red[tid + t];
        __syncthreads();
    }
    float rms = rsqrtf(red[0] / (float)D_MODEL + 1e-8f);

    float4 gg = g4[tid];
    float4 o;
    o.x = s.x * rms * gg.x; o.y = s.y * rms * gg.y;
    o.z = s.z * rms * gg.z; o.w = s.w * rms * gg.w;
    o4[tid] = o;
}

// ---------------------------------------------------------------------------
// kernel_launch
// Inputs (metadata order): x, mask, Wq, bq, Wk, bk, Wv, bv, Wo, bo,
//                          g1, W1, b1, W2, b2, g2
// Output: [ y (B*S*D fp32) | attn (B*H*S*S fp32) ]
// ---------------------------------------------------------------------------
extern "C" void kernel_launch(void* const* d_in, const int* in_sizes, int n_in,
                              void* d_out, int out_size)
{
    (void)in_sizes; (void)n_in; (void)out_size;

    const float* x    = (const float*)d_in[0];
    const int*   mask = (const int*)  d_in[1];
    const float* Wq   = (const float*)d_in[2];
    const float* bq   = (const float*)d_in[3];
    const float* Wk   = (const float*)d_in[4];
    const float* bk   = (const float*)d_in[5];
    const float* Wv   = (const float*)d_in[6];
    const float* bv   = (const float*)d_in[7];
    const float* Wo   = (const float*)d_in[8];
    const float* bo   = (const float*)d_in[9];
    const float* g1   = (const float*)d_in[10];
    const float* W1   = (const float*)d_in[11];
    const float* b1   = (const float*)d_in[12];
    const float* W2   = (const float*)d_in[13];
    const float* b2   = (const float*)d_in[14];
    const float* g2   = (const float*)d_in[15];

    float* y_out = (float*)d_out;
    float* attn  = y_out + (long long)M_ROWS * D_MODEL;

    float *q, *k, *v, *ctx, *tmp, *h1, *ffn1;
    cudaGetSymbolAddress((void**)&q,    g_q);
    cudaGetSymbolAddress((void**)&k,    g_k);
    cudaGetSymbolAddress((void**)&v,    g_v);
    cudaGetSymbolAddress((void**)&ctx,  g_ctx);
    cudaGetSymbolAddress((void**)&tmp,  g_tmp);
    cudaGetSymbolAddress((void**)&h1,   g_h1);
    cudaGetSymbolAddress((void**)&ffn1, g_ffn1);

    const long long SD  = (long long)S_LEN * D_MODEL;     // per-batch token block
    const long long SS  = (long long)S_LEN * S_LEN;       // per-head attn matrix
    const long long HSS = (long long)N_HEAD * SS;

    // 1) QKV projections: (4096x1024) @ (1024x1024) + bias
    {
        dim3 grid(D_MODEL / 128, M_ROWS / 128, 1);
        gemm_kernel<128,128,16,8,8,false,false><<<grid, 256>>>(
            x, D_MODEL, Wq, D_MODEL, q, D_MODEL, D_MODEL, bq,
            1, 0,0, 0,0, 0,0);
        gemm_kernel<128,128,16,8,8,false,false><<<grid, 256>>>(
            x, D_MODEL, Wk, D_MODEL, k, D_MODEL, D_MODEL, bk,
            1, 0,0, 0,0, 0,0);
        gemm_kernel<128,128,16,8,8,false,false><<<grid, 256>>>(
            x, D_MODEL, Wv, D_MODEL, v, D_MODEL, D_MODEL, bv,
            1, 0,0, 0,0, 0,0);
    }

    // 2) scores = Q_h @ K_h^T  (batched over B*H, K=64) -> write raw into attn
    {
        dim3 grid(S_LEN / 128, S_LEN / 128, B_SZ * N_HEAD);
        gemm_kernel<128,128,16,8,8,true,false><<<grid, 256>>>(
            q, D_MODEL, k, D_MODEL, attn, S_LEN, D_HEAD, nullptr,
            N_HEAD, SD, D_HEAD, SD, D_HEAD, HSS, SS);
    }

    // 3) masked scaled softmax in-place on attn (also the second output)
    softmax_kernel<<<B_SZ * N_HEAD * S_LEN, 256>>>(attn, mask, 0.125f);

    // 4) ctx_h = attn_h @ V_h  (batched, N=64)
    {
        dim3 grid(1, S_LEN / 128, B_SZ * N_HEAD);
        gemm_kernel<128,64,16,8,4,false,false><<<grid, 256>>>(
            attn, S_LEN, v, D_MODEL, ctx, D_MODEL, S_LEN, nullptr,
            N_HEAD, HSS, SS, SD, D_HEAD, SD, D_HEAD);
    }

    // 5) attn_out = ctx @ Wo + bo
    {
        dim3 grid(D_MODEL / 128, M_ROWS / 128, 1);
        gemm_kernel<128,128,16,8,8,false,false><<<grid, 256>>>(
            ctx, D_MODEL, Wo, D_MODEL, tmp, D_MODEL, D_MODEL, bo,
            1, 0,0, 0,0, 0,0);
    }

    // 6) h1 = rmsnorm(x + attn_out, g1)
    add_rmsnorm_kernel<<<M_ROWS, 256>>>(x, tmp, g1, h1);

    // 7) ffn1 = relu(h1 @ W1 + b1)   (4096x4096x1024)
    {
        dim3 grid(F_DIM / 128, M_ROWS / 128, 1);
        gemm_kernel<128,128,16,8,8,false,true><<<grid, 256>>>(
            h1, D_MODEL, W1, F_DIM, ffn1, F_DIM, D_MODEL, b1,
            1, 0,0, 0,0, 0,0);
    }

    // 8) ffn2 = ffn1 @ W2 + b2       (4096x1024x4096)
    {
        dim3 grid(D_MODEL / 128, M_ROWS / 128, 1);
        gemm_kernel<128,128,16,8,8,false,false><<<grid, 256>>>(
            ffn1, F_DIM, W2, D_MODEL, tmp, D_MODEL, F_DIM, b2,
            1, 0,0, 0,0, 0,0);
    }

    // 9) y = rmsnorm(h1 + ffn2, g2)
    add_rmsnorm_kernel<<<M_ROWS, 256>>>(h1, tmp, g2, y_out);
}

// round 5
// speedup vs baseline: 2.2621x; 2.2621x over previous
#include <cuda_runtime.h>
#include <cuda_bf16.h>
#include <math.h>
#include <stdint.h>

// ---------------- problem constants ----------------
#define B_SZ    2
#define S_LEN   2048
#define D_MODEL 1024
#define N_HEAD  16
#define D_HEAD  64
#define F_DIM   4096
#define M_ROWS  (B_SZ * S_LEN)                     // 4096
typedef __nv_bfloat16 bf16;

#define ATTN_ELEMS ((long long)B_SZ * N_HEAD * S_LEN * S_LEN)   // 134217728

// ---------------- scratch (device globals; alloc-free) ----------------
__device__ __align__(256) bf16 g_xh [M_ROWS * D_MODEL], g_xl [M_ROWS * D_MODEL];
__device__ __align__(256) bf16 g_wqh[D_MODEL * D_MODEL], g_wql[D_MODEL * D_MODEL];
__device__ __align__(256) bf16 g_wkh[D_MODEL * D_MODEL], g_wkl[D_MODEL * D_MODEL];
__device__ __align__(256) bf16 g_wvh[D_MODEL * D_MODEL], g_wvl[D_MODEL * D_MODEL];
__device__ __align__(256) bf16 g_woh[D_MODEL * D_MODEL], g_wol[D_MODEL * D_MODEL];
__device__ __align__(256) bf16 g_w1h[D_MODEL * F_DIM],   g_w1l[D_MODEL * F_DIM];
__device__ __align__(256) bf16 g_w2h[D_MODEL * F_DIM],   g_w2l[D_MODEL * F_DIM];
__device__ __align__(256) bf16 g_qh [M_ROWS * D_MODEL],  g_ql [M_ROWS * D_MODEL];
__device__ __align__(256) bf16 g_kh [M_ROWS * D_MODEL],  g_kl [M_ROWS * D_MODEL];
__device__ __align__(256) bf16 g_vh [M_ROWS * D_MODEL],  g_vl [M_ROWS * D_MODEL];
__device__ __align__(256) bf16 g_vth[M_ROWS * D_MODEL],  g_vtl[M_ROWS * D_MODEL];
__device__ __align__(256) bf16 g_ah [ATTN_ELEMS],        g_al [ATTN_ELEMS];
__device__ __align__(256) bf16 g_ch [M_ROWS * D_MODEL],  g_cl [M_ROWS * D_MODEL];
__device__ __align__(256) bf16 g_h1h[M_ROWS * D_MODEL],  g_h1l[M_ROWS * D_MODEL];
__device__ __align__(256) bf16 g_f1h[M_ROWS * F_DIM],    g_f1l[M_ROWS * F_DIM];
__device__ __align__(256) float g_h1 [M_ROWS * D_MODEL];
__device__ __align__(256) float g_tmp[M_ROWS * D_MODEL];

// ---------------- base-ISA PTX helpers (NO "a"-suffix features) ----------------
__device__ __forceinline__ uint32_t smem_to_u32(const void* p) {
    uint32_t a;
    asm("{ .reg .u64 t; cvta.to.shared.u64 t, %1; cvt.u32.u64 %0, t; }"
        : "=r"(a) : "l"(p));
    return a;
}
__device__ __forceinline__ void cp16(uint32_t smem, const void* g) {
    asm volatile("cp.async.cg.shared.global [%0], [%1], 16;" :: "r"(smem), "l"(g));
}
__device__ __forceinline__ void cp_commit() {
    asm volatile("cp.async.commit_group;" ::: "memory");
}
__device__ __forceinline__ void ldmx4(uint32_t addr, uint32_t r[4]) {
    asm volatile("ldmatrix.sync.aligned.m8n8.x4.shared.b16 {%0,%1,%2,%3}, [%4];"
                 : "=r"(r[0]), "=r"(r[1]), "=r"(r[2]), "=r"(r[3]) : "r"(addr));
}
__device__ __forceinline__ void mma16816(float c[4], const uint32_t a[4],
                                         const uint32_t b[2]) {
    asm volatile(
        "mma.sync.aligned.m16n8k16.row.col.f32.bf16.bf16.f32 "
        "{%0,%1,%2,%3}, {%4,%5,%6,%7}, {%8,%9}, {%0,%1,%2,%3};"
        : "+f"(c[0]), "+f"(c[1]), "+f"(c[2]), "+f"(c[3])
        : "r"(a[0]), "r"(a[1]), "r"(a[2]), "r"(a[3]), "r"(b[0]), "r"(b[1]));
}
__device__ __forceinline__ void split2(float v, bf16& h, bf16& l) {
    h = __float2bfloat16(v);
    l = __float2bfloat16(v - __bfloat162float(h));
}
__device__ __forceinline__ uint32_t pack2(bf16 a, bf16 b) {
    return (uint32_t)__bfloat16_as_ushort(a) | ((uint32_t)__bfloat16_as_ushort(b) << 16);
}

// stage ROWS x 64 bf16 tile (128B rows) into SW128-swizzled smem via cp.async
template<int ROWS>
__device__ __forceinline__ void stage_tile(uint32_t dst, const bf16* __restrict__ g,
                                           int ld, int tid) {
    constexpr int ITERS = (ROWS * 8) / 256;
#pragma unroll
    for (int it = 0; it < ITERS; it++) {
        int idx = it * 256 + tid;
        int r = idx >> 3, c = idx & 7;
        uint32_t off = (uint32_t)(r * 128 + ((c ^ (r & 7)) << 4));
        cp16(dst + off, g + (long long)r * ld + c * 8);
    }
}

// ---------------- HMMA split-bf16 GEMM ----------------
// C[128 x BN] = (Ahi+Alo)[M x K] @ (Bhi+Blo)[N x K]^T, fp32 accum.
// 3-term: AhBh + AlBh + AhBl. BK = 64. 256 threads, 8 warps (4m x 2n).
template<int BN, bool RELU, bool WF32, bool WBF16>
__global__ __launch_bounds__(256)
void gemm_mma(const bf16* __restrict__ Ahi, const bf16* __restrict__ Alo, int lda,
              const bf16* __restrict__ Bhi, const bf16* __restrict__ Blo, int ldb,
              float* __restrict__ C, bf16* __restrict__ Chi, bf16* __restrict__ Clo,
              int ldc, int K, const float* __restrict__ bias, int batchH,
              long long sAb, long long sAh, long long sBb, long long sBh,
              long long sCb, long long sCh)
{
    constexpr int WN = BN / 2;            // warp tile n
    constexpr int NF = WN / 8;            // n-fragments per warp
    constexpr int TILE_A = 128 * 128;     // bytes per 128x64 bf16 matrix
    constexpr int TILE_B = BN * 128;
    constexpr int STAGE  = 2 * TILE_A + 2 * TILE_B;

    extern __shared__ char smem[];
    const uint32_t sb = smem_to_u32(smem);
    const int tid = threadIdx.x, lane = tid & 31, wid = tid >> 5;
    const int wm = wid & 3, wn = wid >> 2;

    const int z = blockIdx.z, zb = z / batchH, zh = z - zb * batchH;
    Ahi += zb * sAb + zh * sAh;  Alo += zb * sAb + zh * sAh;
    Bhi += zb * sBb + zh * sBh;  Blo += zb * sBb + zh * sBh;
    const long long coff = zb * sCb + zh * sCh;
    const int m0 = blockIdx.y * 128, n0 = blockIdx.x * BN;

    auto issue = [&](int stg, int k0) {
        uint32_t st = sb + stg * STAGE;
        stage_tile<128>(st,                       Ahi + (long long)m0 * lda + k0, lda, tid);
        stage_tile<128>(st + TILE_A,              Alo + (long long)m0 * lda + k0, lda, tid);
        stage_tile<BN> (st + 2 * TILE_A,          Bhi + (long long)n0 * ldb + k0, ldb, tid);
        stage_tile<BN> (st + 2 * TILE_A + TILE_B, Blo + (long long)n0 * ldb + k0, ldb, tid);
        cp_commit();
    };

    float c[2][NF][4];
#pragma unroll
    for (int mb = 0; mb < 2; mb++)
#pragma unroll
        for (int nf = 0; nf < NF; nf++)
#pragma unroll
            for (int j = 0; j < 4; j++) c[mb][nf][j] = 0.f;

    const int nch = K >> 6;
    issue(0, 0);
    if (nch > 1) issue(1, 64);

    const int arow = wm * 32 + (lane & 15);
    const int brow = wn * WN + (lane & 15);
    const int csel = lane >> 4;

    for (int i = 0; i < nch; i++) {
        const int buf = i & 1;
        if (i + 1 < nch) asm volatile("cp.async.wait_group 1;" ::: "memory");
        else             asm volatile("cp.async.wait_group 0;" ::: "memory");
        __syncthreads();

        const uint32_t aB  = sb + buf * STAGE;
        const uint32_t alB = aB + TILE_A;
        const uint32_t bB  = aB + 2 * TILE_A;
        const uint32_t blB = bB + TILE_B;

#pragma unroll
        for (int ks = 0; ks < 4; ks++) {
            const int ch = ks * 2 + csel;
            uint32_t ah[2][4], alr[2][4];
#pragma unroll
            for (int mb = 0; mb < 2; mb++) {
                int r = arow + mb * 16;
                uint32_t off = (uint32_t)(r * 128 + ((ch ^ (r & 7)) << 4));
                ldmx4(aB + off, ah[mb]);
                ldmx4(alB + off, alr[mb]);
            }
            uint32_t bh[NF][2], blr[NF][2];
#pragma unroll
            for (int nb = 0; nb < NF / 2; nb++) {
                int r = brow + nb * 16;
                uint32_t off = (uint32_t)(r * 128 + ((ch ^ (r & 7)) << 4));
                uint32_t t[4];
                ldmx4(bB + off, t);
                bh[2*nb][0] = t[0]; bh[2*nb+1][0] = t[1];
                bh[2*nb][1] = t[2]; bh[2*nb+1][1] = t[3];
                ldmx4(blB + off, t);
                blr[2*nb][0] = t[0]; blr[2*nb+1][0] = t[1];
                blr[2*nb][1] = t[2]; blr[2*nb+1][1] = t[3];
            }
#pragma unroll
            for (int mb = 0; mb < 2; mb++)
#pragma unroll
                for (int nf = 0; nf < NF; nf++) {
                    mma16816(c[mb][nf], ah[mb],  bh[nf]);
                    mma16816(c[mb][nf], alr[mb], bh[nf]);
                    mma16816(c[mb][nf], ah[mb],  blr[nf]);
                }
        }
        __syncthreads();
        if (i + 2 < nch) issue(buf, (i + 2) << 6);
    }

    // ---- epilogue: direct fragment stores (bias / ReLU / hi-lo split) ----
#pragma unroll
    for (int mb = 0; mb < 2; mb++) {
        int row = m0 + wm * 32 + mb * 16 + (lane >> 2);
#pragma unroll
        for (int nf = 0; nf < NF; nf++) {
            int col = n0 + wn * WN + nf * 8 + 2 * (lane & 3);
            float b0 = bias ? bias[col] : 0.f;
            float b1 = bias ? bias[col + 1] : 0.f;
            float v0 = c[mb][nf][0] + b0, v1 = c[mb][nf][1] + b1;
            float v2 = c[mb][nf][2] + b0, v3 = c[mb][nf][3] + b1;
            if (RELU) {
                v0 = fmaxf(v0, 0.f); v1 = fmaxf(v1, 0.f);
                v2 = fmaxf(v2, 0.f); v3 = fmaxf(v3, 0.f);
            }
            long long o0 = coff + (long long)row * ldc + col;
            long long o1 = o0 + 8LL * ldc;
            if (WF32) {
                float2 f0; f0.x = v0; f0.y = v1;
                float2 f1; f1.x = v2; f1.y = v3;
                *reinterpret_cast<float2*>(C + o0) = f0;
                *reinterpret_cast<float2*>(C + o1) = f1;
            }
            if (WBF16) {
                bf16 h0, l0, h1, l1;
                split2(v0, h0, l0); split2(v1, h1, l1);
                *reinterpret_cast<uint32_t*>(Chi + o0) = pack2(h0, h1);
                *reinterpret_cast<uint32_t*>(Clo + o0) = pack2(l0, l1);
                split2(v2, h0, l0); split2(v3, h1, l1);
                *reinterpret_cast<uint32_t*>(Chi + o1) = pack2(h0, h1);
                *reinterpret_cast<uint32_t*>(Clo + o1) = pack2(l0, l1);
            }
        }
    }
}

// ---------------- conversion / transpose kernels ----------------
__global__ void split_f32(const float* __restrict__ in, bf16* __restrict__ hi,
                          bf16* __restrict__ lo, int n4)
{
    int i = blockIdx.x * 256 + threadIdx.x;
    if (i >= n4) return;
    float4 v = reinterpret_cast<const float4*>(in)[i];
    bf16 h[4], l[4];
    split2(v.x, h[0], l[0]); split2(v.y, h[1], l[1]);
    split2(v.z, h[2], l[2]); split2(v.w, h[3], l[3]);
    uint2 uh; uh.x = pack2(h[0], h[1]); uh.y = pack2(h[2], h[3]);
    uint2 ul; ul.x = pack2(l[0], l[1]); ul.y = pack2(l[2], l[3]);
    reinterpret_cast<uint2*>(hi)[i] = uh;
    reinterpret_cast<uint2*>(lo)[i] = ul;
}

// in fp32 [R][C] -> out bf16 hi/lo [C][R]
__global__ void transpose_split(const float* __restrict__ in, bf16* __restrict__ ohi,
                                bf16* __restrict__ olo, int R, int C)
{
    __shared__ float t[32][33];
    int r0 = blockIdx.y * 32, c0 = blockIdx.x * 32;
    int tx = threadIdx.x, ty = threadIdx.y;
#pragma unroll
    for (int j = 0; j < 32; j += 8)
        t[ty + j][tx] = in[(long long)(r0 + ty + j) * C + c0 + tx];
    __syncthreads();
#pragma unroll
    for (int j = 0; j < 32; j += 8) {
        float v = t[tx][ty + j];
        long long o = (long long)(c0 + ty + j) * R + r0 + tx;
        bf16 h, l; split2(v, h, l);
        ohi[o] = h; olo[o] = l;
    }
}

// v bf16 [B*S][D_MODEL] -> vt bf16 [b,h][64][2048]
__global__ void transpose_v(const bf16* __restrict__ in, bf16* __restrict__ out)
{
    __shared__ bf16 t[32][33];
    int z = blockIdx.z, b = z >> 4, h = z & 15;
    int s0 = blockIdx.x * 32, d0 = blockIdx.y * 32;
    int tx = threadIdx.x, ty = threadIdx.y;
#pragma unroll
    for (int j = 0; j < 32; j += 8)
        t[ty + j][tx] = in[(long long)(b * S_LEN + s0 + ty + j) * D_MODEL + h * D_HEAD + d0 + tx];
    __syncthreads();
    long long ob = (long long)z * D_HEAD * S_LEN;
#pragma unroll
    for (int j = 0; j < 32; j += 8)
        out[ob + (long long)(d0 + ty + j) * S_LEN + s0 + tx] = t[tx][ty + j];
}

// masked scaled softmax in-place + hi/lo split outputs
__global__ void softmax_split(float* __restrict__ attn, const int* __restrict__ mask,
                              bf16* __restrict__ ahi, bf16* __restrict__ alo, float scale)
{
    const long long r = blockIdx.x;
    const int b = (int)(r / (N_HEAD * S_LEN));
    float* row = attn + r * S_LEN;
    const int* mrow = mask + b * S_LEN;
    const int tid = threadIdx.x;
    constexpr int PER = S_LEN / 256;

    __shared__ float red[256];
    float vals[PER];
    float vmax = -INFINITY;
#pragma unroll
    for (int i = 0; i < PER; i++) {
        int j = i * 256 + tid;
        float v = row[j] * scale;
        if (mrow[j] == 0) v = -INFINITY;
        vals[i] = v;
        vmax = fmaxf(vmax, v);
    }
    red[tid] = vmax; __syncthreads();
    for (int s = 128; s > 0; s >>= 1) {
        if (tid < s) red[tid] = fmaxf(red[tid], red[tid + s]);
        __syncthreads();
    }
    vmax = red[0]; __syncthreads();
    float sum = 0.f;
#pragma unroll
    for (int i = 0; i < PER; i++) { float e = expf(vals[i] - vmax); vals[i] = e; sum += e; }
    red[tid] = sum; __syncthreads();
    for (int s = 128; s > 0; s >>= 1) {
        if (tid < s) red[tid] += red[tid + s];
        __syncthreads();
    }
    float inv = 1.f / red[0];
#pragma unroll
    for (int i = 0; i < PER; i++) {
        int j = i * 256 + tid;
        float v = vals[i] * inv;
        row[j] = v;
        bf16 h, l; split2(v, h, l);
        ahi[r * S_LEN + j] = h;
        alo[r * S_LEN + j] = l;
    }
}

// out = rmsnorm(xa + xb, g); optional bf16 hi/lo split outputs
__global__ void add_rmsnorm_split(const float* __restrict__ xa, const float* __restrict__ xb,
                                  const float* __restrict__ g, float* __restrict__ out,
                                  bf16* __restrict__ ohi, bf16* __restrict__ olo)
{
    const int r = blockIdx.x, tid = threadIdx.x;   // 256 threads = D/4
    const float4* a4 = reinterpret_cast<const float4*>(xa + (long long)r * D_MODEL);
    const float4* b4 = reinterpret_cast<const float4*>(xb + (long long)r * D_MODEL);
    const float4* g4 = reinterpret_cast<const float4*>(g);
    float4 a = a4[tid], b = b4[tid];
    float4 s; s.x = a.x + b.x; s.y = a.y + b.y; s.z = a.z + b.z; s.w = a.w + b.w;
    float ss = s.x * s.x + s.y * s.y + s.z * s.z + s.w * s.w;

    __shared__ float red[256];
    red[tid] = ss; __syncthreads();
    for (int t = 128; t > 0; t >>= 1) {
        if (tid < t) red[tid] += red[tid + t];
        __syncthreads();
    }
    float rms = rsqrtf(red[0] / (float)D_MODEL + 1e-8f);
    float4 gg = g4[tid];
    float4 o; o.x = s.x * rms * gg.x; o.y = s.y * rms * gg.y;
    o.z = s.z * rms * gg.z; o.w = s.w * rms * gg.w;
    reinterpret_cast<float4*>(out + (long long)r * D_MODEL)[tid] = o;
    if (ohi) {
        bf16 h[4], l[4];
        split2(o.x, h[0], l[0]); split2(o.y, h[1], l[1]);
        split2(o.z, h[2], l[2]); split2(o.w, h[3], l[3]);
        uint2 uh; uh.x = pack2(h[0], h[1]); uh.y = pack2(h[2], h[3]);
        uint2 ul; ul.x = pack2(l[0], l[1]); ul.y = pack2(l[2], l[3]);
        reinterpret_cast<uint2*>(ohi + (long long)r * D_MODEL)[tid] = uh;
        reinterpret_cast<uint2*>(olo + (long long)r * D_MODEL)[tid] = ul;
    }
}

// ---------------- host ----------------
#define STAGE_BN128 (2 * 128 * 128 + 2 * 128 * 128)   // 65536
#define STAGE_BN64  (2 * 128 * 128 + 2 * 64 * 128)    // 49152
#define SMEM_BN128  (2 * STAGE_BN128)                 // 131072
#define SMEM_BN64   (2 * STAGE_BN64)                  // 98304

extern "C" void kernel_launch(void* const* d_in, const int* in_sizes, int n_in,
                              void* d_out, int out_size)
{
    (void)in_sizes; (void)n_in; (void)out_size;
    const float* x  = (const float*)d_in[0];
    const int* mask = (const int*)  d_in[1];
    const float* Wq = (const float*)d_in[2];  const float* bq = (const float*)d_in[3];
    const float* Wk = (const float*)d_in[4];  const float* bk = (const float*)d_in[5];
    const float* Wv = (const float*)d_in[6];  const float* bv = (const float*)d_in[7];
    const float* Wo = (const float*)d_in[8];  const float* bo = (const float*)d_in[9];
    const float* g1 = (const float*)d_in[10];
    const float* W1 = (const float*)d_in[11]; const float* b1 = (const float*)d_in[12];
    const float* W2 = (const float*)d_in[13]; const float* b2 = (const float*)d_in[14];
    const float* g2 = (const float*)d_in[15];

    float* y_out = (float*)d_out;
    float* attn  = y_out + (long long)M_ROWS * D_MODEL;

    bf16 *xh,*xl,*wqh,*wql,*wkh,*wkl,*wvh,*wvl,*woh,*wol,*w1h,*w1l,*w2h,*w2l;
    bf16 *qh,*ql,*kh,*kl,*vh,*vl,*vth,*vtl,*ah,*al,*ch,*cl,*h1h,*h1l,*f1h,*f1l;
    float *h1,*tmp;
    cudaGetSymbolAddress((void**)&xh, g_xh);   cudaGetSymbolAddress((void**)&xl, g_xl);
    cudaGetSymbolAddress((void**)&wqh, g_wqh); cudaGetSymbolAddress((void**)&wql, g_wql);
    cudaGetSymbolAddress((void**)&wkh, g_wkh); cudaGetSymbolAddress((void**)&wkl, g_wkl);
    cudaGetSymbolAddress((void**)&wvh, g_wvh); cudaGetSymbolAddress((void**)&wvl, g_wvl);
    cudaGetSymbolAddress((void**)&woh, g_woh); cudaGetSymbolAddress((void**)&wol, g_wol);
    cudaGetSymbolAddress((void**)&w1h, g_w1h); cudaGetSymbolAddress((void**)&w1l, g_w1l);
    cudaGetSymbolAddress((void**)&w2h, g_w2h); cudaGetSymbolAddress((void**)&w2l, g_w2l);
    cudaGetSymbolAddress((void**)&qh, g_qh);   cudaGetSymbolAddress((void**)&ql, g_ql);
    cudaGetSymbolAddress((void**)&kh, g_kh);   cudaGetSymbolAddress((void**)&kl, g_kl);
    cudaGetSymbolAddress((void**)&vh, g_vh);   cudaGetSymbolAddress((void**)&vl, g_vl);
    cudaGetSymbolAddress((void**)&vth, g_vth); cudaGetSymbolAddress((void**)&vtl, g_vtl);
    cudaGetSymbolAddress((void**)&ah, g_ah);   cudaGetSymbolAddress((void**)&al, g_al);
    cudaGetSymbolAddress((void**)&ch, g_ch);   cudaGetSymbolAddress((void**)&cl, g_cl);
    cudaGetSymbolAddress((void**)&h1h, g_h1h); cudaGetSymbolAddress((void**)&h1l, g_h1l);
    cudaGetSymbolAddress((void**)&f1h, g_f1h); cudaGetSymbolAddress((void**)&f1l, g_f1l);
    cudaGetSymbolAddress((void**)&h1, g_h1);   cudaGetSymbolAddress((void**)&tmp, g_tmp);

    cudaFuncSetAttribute(gemm_mma<128,false,false,true>,
                         cudaFuncAttributeMaxDynamicSharedMemorySize, SMEM_BN128);
    cudaFuncSetAttribute(gemm_mma<128,false,true,false>,
                         cudaFuncAttributeMaxDynamicSharedMemorySize, SMEM_BN128);
    cudaFuncSetAttribute(gemm_mma<128,true,false,true>,
                         cudaFuncAttributeMaxDynamicSharedMemorySize, SMEM_BN128);
    cudaFuncSetAttribute(gemm_mma<64,false,false,true>,
                         cudaFuncAttributeMaxDynamicSharedMemorySize, SMEM_BN64);

    const long long SD  = (long long)S_LEN * D_MODEL;
    const long long SS  = (long long)S_LEN * S_LEN;
    const long long HSS = (long long)N_HEAD * SS;

    // --- input conversions ---
    split_f32<<<(M_ROWS * D_MODEL / 4 + 255) / 256, 256>>>(x, xh, xl, M_ROWS * D_MODEL / 4);
    dim3 tb(32, 8);
    transpose_split<<<dim3(D_MODEL/32, D_MODEL/32), tb>>>(Wq, wqh, wql, D_MODEL, D_MODEL);
    transpose_split<<<dim3(D_MODEL/32, D_MODEL/32), tb>>>(Wk, wkh, wkl, D_MODEL, D_MODEL);
    transpose_split<<<dim3(D_MODEL/32, D_MODEL/32), tb>>>(Wv, wvh, wvl, D_MODEL, D_MODEL);
    transpose_split<<<dim3(D_MODEL/32, D_MODEL/32), tb>>>(Wo, woh, wol, D_MODEL, D_MODEL);
    transpose_split<<<dim3(F_DIM/32,   D_MODEL/32), tb>>>(W1, w1h, w1l, D_MODEL, F_DIM);
    transpose_split<<<dim3(D_MODEL/32, F_DIM/32),   tb>>>(W2, w2h, w2l, F_DIM, D_MODEL);

    // --- QKV projections ---
    {
        dim3 g(D_MODEL/128, M_ROWS/128, 1);
        gemm_mma<128,false,false,true><<<g, 256, SMEM_BN128>>>(
            xh, xl, D_MODEL, wqh, wql, D_MODEL, nullptr, qh, ql, D_MODEL,
            D_MODEL, bq, 1, 0,0, 0,0, 0,0);
        gemm_mma<128,false,false,true><<<g, 256, SMEM_BN128>>>(
            xh, xl, D_MODEL, wkh, wkl, D_MODEL, nullptr, kh, kl, D_MODEL,
            D_MODEL, bk, 1, 0,0, 0,0, 0,0);
        gemm_mma<128,false,false,true><<<g, 256, SMEM_BN128>>>(
            xh, xl, D_MODEL, wvh, wvl, D_MODEL, nullptr, vh, vl, D_MODEL,
            D_MODEL, bv, 1, 0,0, 0,0, 0,0);
    }
    transpose_v<<<dim3(S_LEN/32, D_HEAD/32, B_SZ*N_HEAD), tb>>>(vh, vth);
    transpose_v<<<dim3(S_LEN/32, D_HEAD/32, B_SZ*N_HEAD), tb>>>(vl, vtl);

    // --- scores = Q @ K^T (fp32 into attn output region) ---
    {
        dim3 g(S_LEN/128, S_LEN/128, B_SZ * N_HEAD);
        gemm_mma<128,false,true,false><<<g, 256, SMEM_BN128>>>(
            qh, ql, D_MODEL, kh, kl, D_MODEL, attn, nullptr, nullptr, S_LEN,
            D_HEAD, nullptr, N_HEAD, SD, D_HEAD, SD, D_HEAD, HSS, SS);
    }
    // --- softmax (in-place) + bf16 hi/lo split ---
    softmax_split<<<B_SZ * N_HEAD * S_LEN, 256>>>(attn, mask, ah, al, 0.125f);

    // --- ctx = attn @ V ---
    {
        dim3 g(1, S_LEN/128, B_SZ * N_HEAD);
        gemm_mma<64,false,false,true><<<g, 256, SMEM_BN64>>>(
            ah, al, S_LEN, vth, vtl, S_LEN, nullptr, ch, cl, D_MODEL,
            S_LEN, nullptr, N_HEAD, HSS, SS, (long long)N_HEAD*D_HEAD*S_LEN,
            (long long)D_HEAD*S_LEN, SD, D_HEAD);
    }
    // --- attn_out = ctx @ Wo + bo ---
    {
        dim3 g(D_MODEL/128, M_ROWS/128, 1);
        gemm_mma<128,false,true,false><<<g, 256, SMEM_BN128>>>(
            ch, cl, D_MODEL, woh, wol, D_MODEL, tmp, nullptr, nullptr, D_MODEL,
            D_MODEL, bo, 1, 0,0, 0,0, 0,0);
    }
    // --- h1 = rmsnorm(x + attn_out, g1) ---
    add_rmsnorm_split<<<M_ROWS, 256>>>(x, tmp, g1, h1, h1h, h1l);

    // --- ffn1 = relu(h1 @ W1 + b1) ---
    {
        dim3 g(F_DIM/128, M_ROWS/128, 1);
        gemm_mma<128,true,false,true><<<g, 256, SMEM_BN128>>>(
            h1h, h1l, D_MODEL, w1h, w1l, D_MODEL, nullptr, f1h, f1l, F_DIM,
            D_MODEL, b1, 1, 0,0, 0,0, 0,0);
    }
    // --- ffn2 = ffn1 @ W2 + b2 ---
    {
        dim3 g(D_MODEL/128, M_ROWS/128, 1);
        gemm_mma<128,false,true,false><<<g, 256, SMEM_BN128>>>(
            f1h, f1l, F_DIM, w2h, w2l, F_DIM, tmp, nullptr, nullptr, D_MODEL,
            F_DIM, b2, 1, 0,0, 0,0, 0,0);
    }
    // --- y = rmsnorm(h1 + ffn2, g2) ---
    add_rmsnorm_split<<<M_ROWS, 256>>>(h1, tmp, g2, y_out, nullptr, nullptr);
}